// round 5
// baseline (speedup 1.0000x reference)
#include <cuda_runtime.h>
#include <cstdint>

// Problem constants (shapes fixed by dataset).
constexpr int Hdim   = 128;
constexpr int NLEAF  = 8192;
constexpr int NBATCH = 8;
constexpr int NL     = NBATCH * NLEAF;     // 65536 leaf edges
constexpr int NPT    = 24575;              // nodes per tree
constexpr int NN     = NBATCH * NPT;       // 196600 total nodes
constexpr int DEPTH  = 14;

constexpr int ASTR_BIG   = 260;            // smem stride for 256-wide inputs
constexpr int ASTR_SMALL = 132;            // smem stride for 128/129-wide

// smem sizes: activations + 64x128 weight chunk
constexpr int SMEM_B01_64 = (64 * ASTR_BIG   + 64 * Hdim) * 4;  // 99328
constexpr int SMEM_B01_32 = (32 * ASTR_BIG   + 64 * Hdim) * 4;  // 66048
constexpr int SMEM_B2_64  = (64 * ASTR_SMALL + 64 * Hdim) * 4;  // 66560
constexpr int SMEM_B2_32  = (32 * ASTR_SMALL + 64 * Hdim) * 4;  // 49664
constexpr int SMEM_SMALL  = (16 * ASTR_BIG   + 64 * Hdim) * 4;  // 49408

// ---------------- packed fp32x2 helpers (Blackwell FFMA2) ----------------
typedef unsigned long long ull;

#define FMA_F32X2(d, a, b, c) \
    asm("fma.rn.f32x2 %0, %1, %2, %3;" : "=l"(d) : "l"(a), "l"(b), "l"(c))

#define PACK_DUP_F32X2(out, x) \
    asm("mov.b64 %0, {%1, %1};" : "=l"(out) : "r"(__float_as_uint(x)))

#define UNPACK_F32X2(lo, hi, v) \
    asm("mov.b64 {%0, %1}, %2;" : "=f"(lo), "=f"(hi) : "l"(v))

// ======== BIG kernel: TR-row tiles, 256 threads, RPT x 8 per thread ========

template<int K, int ASTR, int RPT>
__device__ __forceinline__ void layer_acc2(const float* __restrict__ sA,
                                           float* __restrict__ sW,
                                           const float* __restrict__ w,
                                           int tid, int r0, int c0,
                                           ull (&acc)[RPT][4])
{
#pragma unroll 1
    for (int k0 = 0; k0 < K; k0 += 64) {
        // stage 64x128 weight chunk
        for (int idx = tid; idx < 64 * 32; idx += 256) {
            reinterpret_cast<float4*>(sW)[idx] =
                reinterpret_cast<const float4*>(w + (size_t)k0 * Hdim)[idx];
        }
        __syncthreads();
#pragma unroll 2
        for (int kq = 0; kq < 16; ++kq) {
            float4 av[RPT];
#pragma unroll
            for (int i = 0; i < RPT; ++i)
                av[i] = *reinterpret_cast<const float4*>(sA + (r0 + i) * ASTR + k0 + kq * 4);
#pragma unroll
            for (int t = 0; t < 4; ++t) {
                const float* wr = sW + (kq * 4 + t) * Hdim + c0;
                ulonglong2 wA = *reinterpret_cast<const ulonglong2*>(wr);
                ulonglong2 wB = *reinterpret_cast<const ulonglong2*>(wr + 4);
#pragma unroll
                for (int i = 0; i < RPT; ++i) {
                    float a = reinterpret_cast<const float*>(&av[i])[t];
                    ull aa; PACK_DUP_F32X2(aa, a);
                    FMA_F32X2(acc[i][0], aa, wA.x, acc[i][0]);
                    FMA_F32X2(acc[i][1], aa, wA.y, acc[i][1]);
                    FMA_F32X2(acc[i][2], aa, wB.x, acc[i][2]);
                    FMA_F32X2(acc[i][3], aa, wB.y, acc[i][3]);
                }
            }
        }
        __syncthreads();
    }
}

template<int RPT>
__device__ __forceinline__ void zero_acc2(ull (&acc)[RPT][4]) {
#pragma unroll
    for (int i = 0; i < RPT; ++i)
#pragma unroll
        for (int j = 0; j < 4; ++j) acc[i][j] = 0ull;
}

template<int RPT>
__device__ __forceinline__ void epi_bias_relu(ull (&acc)[RPT][4],
                                              const float* __restrict__ b,
                                              float* __restrict__ sA,
                                              int r0, int c0)
{
    float4 bv0 = *reinterpret_cast<const float4*>(b + c0);
    float4 bv1 = *reinterpret_cast<const float4*>(b + c0 + 4);
    const float bv[8] = {bv0.x, bv0.y, bv0.z, bv0.w, bv1.x, bv1.y, bv1.z, bv1.w};
#pragma unroll
    for (int i = 0; i < RPT; ++i) {
        float v[8];
#pragma unroll
        for (int jj = 0; jj < 4; ++jj) {
            float lo, hi; UNPACK_F32X2(lo, hi, acc[i][jj]);
            lo += bv[2 * jj];     hi += bv[2 * jj + 1];
            v[2 * jj]     = lo > 0.f ? lo : 0.f;
            v[2 * jj + 1] = hi > 0.f ? hi : 0.f;
        }
        *reinterpret_cast<float4*>(sA + (r0 + i) * ASTR_SMALL + c0) =
            make_float4(v[0], v[1], v[2], v[3]);
        *reinterpret_cast<float4*>(sA + (r0 + i) * ASTR_SMALL + c0 + 4) =
            make_float4(v[4], v[5], v[6], v[7]);
    }
}

// MODE 0: nem — in=[x[esrc[e]], ef[e]]               (K=256), out -> x[edst[e]]        (set)
// MODE 1: mg  — in=[x[esrc[s+r]], x[esrc[s+half+r]]] (K=256), out -> x[edst[s+half+r]] (set)
// MODE 2: mr  — in=[x[edst[e]], state[e]]            (K=129), out -> x[esrc[e]] += out
template<int MODE, int TR>
__global__ void __launch_bounds__(256, 2)
mlp_big(float* __restrict__ x,
        const float* __restrict__ ef,
        const int* __restrict__ esrc,
        const int* __restrict__ edst,
        const float* __restrict__ est,
        const float* __restrict__ w0, const float* __restrict__ b0,
        const float* __restrict__ w1, const float* __restrict__ b1,
        const float* __restrict__ w2, const float* __restrict__ b2,
        int s, int half, int nrows)
{
    constexpr int RPT   = TR / 16;
    constexpr int ASTR0 = (MODE == 2) ? ASTR_SMALL : ASTR_BIG;
    extern __shared__ float sm[];
    float* sA = sm;
    float* sW = sm + TR * ASTR0;

    const int tid = threadIdx.x;
    const int cx = tid & 15, ry = tid >> 4;      // 16 col-groups x 16 row-groups
    const int c0 = cx * 8, r0 = ry * RPT;
    const int row_base = blockIdx.x * TR;

    // ---- gather inputs into sA ----
    if (MODE == 0 || MODE == 1) {
        for (int idx = tid; idx < TR * 64; idx += 256) {
            int r = idx >> 6, c4 = idx & 63;
            int row = row_base + r;
            if (row < nrows) {
                float4 v;
                if (c4 < 32) {
                    int node = esrc[s + row];
                    v = reinterpret_cast<const float4*>(x + (size_t)node * Hdim)[c4];
                } else if (MODE == 0) {
                    v = reinterpret_cast<const float4*>(ef + (size_t)(s + row) * Hdim)[c4 - 32];
                } else {
                    int node = esrc[s + half + row];
                    v = reinterpret_cast<const float4*>(x + (size_t)node * Hdim)[c4 - 32];
                }
                reinterpret_cast<float4*>(sA + r * ASTR_BIG)[c4] = v;
            }
        }
    } else {
        for (int idx = tid; idx < TR * 32; idx += 256) {
            int r = idx >> 5, c4 = idx & 31;
            int row = row_base + r;
            if (row < nrows) {
                int node = edst[s + row];
                float4 v = reinterpret_cast<const float4*>(x + (size_t)node * Hdim)[c4];
                reinterpret_cast<float4*>(sA + r * ASTR_SMALL)[c4] = v;
            }
        }
        for (int r = tid; r < TR; r += 256) {
            int row = row_base + r;
            sA[r * ASTR_SMALL + 128] = (row < nrows) ? est[s + row] : 0.f;
        }
    }
    __syncthreads();

    ull acc[RPT][4];

    // ---- layer 0 ----
    zero_acc2<RPT>(acc);
    if (MODE == 2) {
        layer_acc2<128, ASTR_SMALL, RPT>(sA, sW, w0, tid, r0, c0, acc);
        // state column: row 128 of w0, straight from global (L2-hot)
        const float* wsr = w0 + (size_t)128 * Hdim + c0;
        ulonglong2 wsA = *reinterpret_cast<const ulonglong2*>(wsr);
        ulonglong2 wsB = *reinterpret_cast<const ulonglong2*>(wsr + 4);
#pragma unroll
        for (int i = 0; i < RPT; ++i) {
            float stv = sA[(r0 + i) * ASTR_SMALL + 128];
            ull aa; PACK_DUP_F32X2(aa, stv);
            FMA_F32X2(acc[i][0], aa, wsA.x, acc[i][0]);
            FMA_F32X2(acc[i][1], aa, wsA.y, acc[i][1]);
            FMA_F32X2(acc[i][2], aa, wsB.x, acc[i][2]);
            FMA_F32X2(acc[i][3], aa, wsB.y, acc[i][3]);
        }
    } else {
        layer_acc2<256, ASTR_BIG, RPT>(sA, sW, w0, tid, r0, c0, acc);
    }
    epi_bias_relu<RPT>(acc, b0, sA, r0, c0);
    __syncthreads();

    // ---- layer 1 ----
    zero_acc2<RPT>(acc);
    layer_acc2<128, ASTR_SMALL, RPT>(sA, sW, w1, tid, r0, c0, acc);
    epi_bias_relu<RPT>(acc, b1, sA, r0, c0);
    __syncthreads();

    // ---- layer 2 + scatter ----
    zero_acc2<RPT>(acc);
    layer_acc2<128, ASTR_SMALL, RPT>(sA, sW, w2, tid, r0, c0, acc);
    {
        float4 bv0 = *reinterpret_cast<const float4*>(b2 + c0);
        float4 bv1 = *reinterpret_cast<const float4*>(b2 + c0 + 4);
        const float bv[8] = {bv0.x, bv0.y, bv0.z, bv0.w, bv1.x, bv1.y, bv1.z, bv1.w};
#pragma unroll
        for (int i = 0; i < RPT; ++i) {
            int row = row_base + r0 + i;
            if (row >= nrows) continue;
            float v[8];
#pragma unroll
            for (int jj = 0; jj < 4; ++jj) {
                float lo, hi; UNPACK_F32X2(lo, hi, acc[i][jj]);
                v[2 * jj]     = lo + bv[2 * jj];
                v[2 * jj + 1] = hi + bv[2 * jj + 1];
            }

            int node;
            if (MODE == 0)      node = edst[s + row];
            else if (MODE == 1) node = edst[s + half + row];
            else                node = esrc[s + row];

            float* p = x + (size_t)node * Hdim + c0;
            if (MODE == 2) {
                float4 o0 = *reinterpret_cast<const float4*>(p);
                float4 o1 = *reinterpret_cast<const float4*>(p + 4);
                v[0] += o0.x; v[1] += o0.y; v[2] += o0.z; v[3] += o0.w;
                v[4] += o1.x; v[5] += o1.y; v[6] += o1.z; v[7] += o1.w;
            }
            *reinterpret_cast<float4*>(p)     = make_float4(v[0], v[1], v[2], v[3]);
            *reinterpret_cast<float4*>(p + 4) = make_float4(v[4], v[5], v[6], v[7]);
        }
    }
}

// =============== SMALL kernel: 16-row tiles, 256 threads, 1x8/thread =======

template<int K, int ASTR>
__device__ __forceinline__ void layer_acc_s(const float* __restrict__ sA,
                                            float* __restrict__ sW,
                                            const float* __restrict__ w,
                                            int tid, int r0, int c0,
                                            float (&acc)[8])
{
#pragma unroll 1
    for (int k0 = 0; k0 < K; k0 += 64) {
        for (int idx = tid; idx < 64 * 32; idx += 256) {
            reinterpret_cast<float4*>(sW)[idx] =
                reinterpret_cast<const float4*>(w + (size_t)k0 * Hdim)[idx];
        }
        __syncthreads();
#pragma unroll 4
        for (int kq = 0; kq < 16; ++kq) {
            float4 av = *reinterpret_cast<const float4*>(sA + r0 * ASTR + k0 + kq * 4);
#pragma unroll
            for (int t = 0; t < 4; ++t) {
                const float* wr = sW + (kq * 4 + t) * Hdim + c0;
                float4 w0v = *reinterpret_cast<const float4*>(wr);
                float4 w1v = *reinterpret_cast<const float4*>(wr + 4);
                float a = reinterpret_cast<const float*>(&av)[t];
                acc[0] = fmaf(a, w0v.x, acc[0]);
                acc[1] = fmaf(a, w0v.y, acc[1]);
                acc[2] = fmaf(a, w0v.z, acc[2]);
                acc[3] = fmaf(a, w0v.w, acc[3]);
                acc[4] = fmaf(a, w1v.x, acc[4]);
                acc[5] = fmaf(a, w1v.y, acc[5]);
                acc[6] = fmaf(a, w1v.z, acc[6]);
                acc[7] = fmaf(a, w1v.w, acc[7]);
            }
        }
        __syncthreads();
    }
}

template<int MODE>
__global__ void __launch_bounds__(256)
mlp_small(float* __restrict__ x,
          const float* __restrict__ ef,
          const int* __restrict__ esrc,
          const int* __restrict__ edst,
          const float* __restrict__ est,
          const float* __restrict__ w0, const float* __restrict__ b0,
          const float* __restrict__ w1, const float* __restrict__ b1,
          const float* __restrict__ w2, const float* __restrict__ b2,
          int s, int half, int nrows)
{
    extern __shared__ float sm[];
    float* sA = sm;
    float* sW = sm + 16 * ASTR_BIG;

    const int tid = threadIdx.x;
    const int cx = tid & 15, ry = tid >> 4;      // 16 col-groups x 16 rows
    const int c0 = cx * 8, r0 = ry;
    const int row_base = blockIdx.x * 16;

    if (MODE == 0 || MODE == 1) {
        for (int idx = tid; idx < 16 * 64; idx += 256) {
            int r = idx >> 6, c4 = idx & 63;
            int row = row_base + r;
            if (row < nrows) {
                float4 v;
                if (c4 < 32) {
                    int node = esrc[s + row];
                    v = reinterpret_cast<const float4*>(x + (size_t)node * Hdim)[c4];
                } else if (MODE == 0) {
                    v = reinterpret_cast<const float4*>(ef + (size_t)(s + row) * Hdim)[c4 - 32];
                } else {
                    int node = esrc[s + half + row];
                    v = reinterpret_cast<const float4*>(x + (size_t)node * Hdim)[c4 - 32];
                }
                reinterpret_cast<float4*>(sA + r * ASTR_BIG)[c4] = v;
            }
        }
    } else {
        for (int idx = tid; idx < 16 * 32; idx += 256) {
            int r = idx >> 5, c4 = idx & 31;
            int row = row_base + r;
            if (row < nrows) {
                int node = edst[s + row];
                float4 v = reinterpret_cast<const float4*>(x + (size_t)node * Hdim)[c4];
                reinterpret_cast<float4*>(sA + r * ASTR_SMALL)[c4] = v;
            }
        }
        for (int r = tid; r < 16; r += 256) {
            int row = row_base + r;
            sA[r * ASTR_SMALL + 128] = (row < nrows) ? est[s + row] : 0.f;
        }
    }
    __syncthreads();

    float acc[8];

    // ---- layer 0 ----
#pragma unroll
    for (int j = 0; j < 8; ++j) acc[j] = 0.f;
    if (MODE == 2) {
        layer_acc_s<128, ASTR_SMALL>(sA, sW, w0, tid, r0, c0, acc);
        const float* wsr = w0 + (size_t)128 * Hdim + c0;
        float stv = sA[r0 * ASTR_SMALL + 128];
#pragma unroll
        for (int j = 0; j < 8; ++j) acc[j] = fmaf(stv, wsr[j], acc[j]);
    } else {
        layer_acc_s<256, ASTR_BIG>(sA, sW, w0, tid, r0, c0, acc);
    }
    {
#pragma unroll
        for (int j = 0; j < 8; ++j) {
            float v = acc[j] + b0[c0 + j];
            acc[j] = v > 0.f ? v : 0.f;
        }
        *reinterpret_cast<float4*>(sA + r0 * ASTR_SMALL + c0) =
            make_float4(acc[0], acc[1], acc[2], acc[3]);
        *reinterpret_cast<float4*>(sA + r0 * ASTR_SMALL + c0 + 4) =
            make_float4(acc[4], acc[5], acc[6], acc[7]);
    }
    __syncthreads();

    // ---- layer 1 ----
#pragma unroll
    for (int j = 0; j < 8; ++j) acc[j] = 0.f;
    layer_acc_s<128, ASTR_SMALL>(sA, sW, w1, tid, r0, c0, acc);
    {
#pragma unroll
        for (int j = 0; j < 8; ++j) {
            float v = acc[j] + b1[c0 + j];
            acc[j] = v > 0.f ? v : 0.f;
        }
        *reinterpret_cast<float4*>(sA + r0 * ASTR_SMALL + c0) =
            make_float4(acc[0], acc[1], acc[2], acc[3]);
        *reinterpret_cast<float4*>(sA + r0 * ASTR_SMALL + c0 + 4) =
            make_float4(acc[4], acc[5], acc[6], acc[7]);
    }
    __syncthreads();

    // ---- layer 2 + scatter ----
#pragma unroll
    for (int j = 0; j < 8; ++j) acc[j] = 0.f;
    layer_acc_s<128, ASTR_SMALL>(sA, sW, w2, tid, r0, c0, acc);
    {
        int row = row_base + r0;
        if (row < nrows) {
#pragma unroll
            for (int j = 0; j < 8; ++j) acc[j] += b2[c0 + j];

            int node;
            if (MODE == 0)      node = edst[s + row];
            else if (MODE == 1) node = edst[s + half + row];
            else                node = esrc[s + row];

            float* p = x + (size_t)node * Hdim + c0;
            if (MODE == 2) {
                float4 o0 = *reinterpret_cast<const float4*>(p);
                float4 o1 = *reinterpret_cast<const float4*>(p + 4);
                acc[0] += o0.x; acc[1] += o0.y; acc[2] += o0.z; acc[3] += o0.w;
                acc[4] += o1.x; acc[5] += o1.y; acc[6] += o1.z; acc[7] += o1.w;
            }
            *reinterpret_cast<float4*>(p)     = make_float4(acc[0], acc[1], acc[2], acc[3]);
            *reinterpret_cast<float4*>(p + 4) = make_float4(acc[4], acc[5], acc[6], acc[7]);
        }
    }
}

// copy only leaf rows of x (everything else is provably overwritten)
__global__ void leaf_copy_kernel(float* __restrict__ x, const float* __restrict__ x_in)
{
    int idx = blockIdx.x * blockDim.x + threadIdx.x;   // over NL*32 float4s
    if (idx >= NL * 32) return;
    int r = idx >> 5, c4 = idx & 31;
    int b = r >> 13, leaf = r & (NLEAF - 1);
    size_t node = (size_t)b * NPT + leaf;
    reinterpret_cast<float4*>(x + node * Hdim)[c4] =
        reinterpret_cast<const float4*>(x_in + node * Hdim)[c4];
}

// ---------------- dispatch helpers ----------------
static inline void launch_big(int MODE, float* x, const float* ef,
                              const int* esrc, const int* edst, const float* est,
                              const float* w0, const float* b0,
                              const float* w1, const float* b1,
                              const float* w2, const float* b2,
                              int s, int half, int nrows)
{
    bool tr32 = (nrows <= 9472);
    if (MODE == 0) {
        if (tr32) mlp_big<0,32><<<(nrows + 31) / 32, 256, SMEM_B01_32>>>(x, ef, esrc, edst, est, w0, b0, w1, b1, w2, b2, s, half, nrows);
        else      mlp_big<0,64><<<(nrows + 63) / 64, 256, SMEM_B01_64>>>(x, ef, esrc, edst, est, w0, b0, w1, b1, w2, b2, s, half, nrows);
    } else if (MODE == 1) {
        if (tr32) mlp_big<1,32><<<(nrows + 31) / 32, 256, SMEM_B01_32>>>(x, ef, esrc, edst, est, w0, b0, w1, b1, w2, b2, s, half, nrows);
        else      mlp_big<1,64><<<(nrows + 63) / 64, 256, SMEM_B01_64>>>(x, ef, esrc, edst, est, w0, b0, w1, b1, w2, b2, s, half, nrows);
    } else {
        if (tr32) mlp_big<2,32><<<(nrows + 31) / 32, 256, SMEM_B2_32>>>(x, ef, esrc, edst, est, w0, b0, w1, b1, w2, b2, s, half, nrows);
        else      mlp_big<2,64><<<(nrows + 63) / 64, 256, SMEM_B2_64>>>(x, ef, esrc, edst, est, w0, b0, w1, b1, w2, b2, s, half, nrows);
    }
}

extern "C" void kernel_launch(void* const* d_in, const int* in_sizes, int n_in,
                              void* d_out, int out_size)
{
    (void)n_in; (void)out_size;

    const float* x_in = (const float*)d_in[0];
    const int*   esrc = (const int*)  d_in[1];
    const int*   edst = (const int*)  d_in[2];
    const float* est  = (const float*)d_in[3];
    const float* ef   = (const float*)d_in[4];

    int wb = (in_sizes[5] == 1) ? 6 : 5;   // input 5 = scalar gcmn_depth

    const float* nem_w0 = (const float*)d_in[wb + 0];
    const float* nem_b0 = (const float*)d_in[wb + 1];
    const float* nem_w1 = (const float*)d_in[wb + 2];
    const float* nem_b1 = (const float*)d_in[wb + 3];
    const float* nem_w2 = (const float*)d_in[wb + 4];
    const float* nem_b2 = (const float*)d_in[wb + 5];
    const float* mg_w0  = (const float*)d_in[wb + 6];
    const float* mg_b0  = (const float*)d_in[wb + 7];
    const float* mg_w1  = (const float*)d_in[wb + 8];
    const float* mg_b1  = (const float*)d_in[wb + 9];
    const float* mg_w2  = (const float*)d_in[wb + 10];
    const float* mg_b2  = (const float*)d_in[wb + 11];
    const float* mr_w0  = (const float*)d_in[wb + 12];
    const float* mr_b0  = (const float*)d_in[wb + 13];
    const float* mr_w1  = (const float*)d_in[wb + 14];
    const float* mr_b1  = (const float*)d_in[wb + 15];
    const float* mr_w2  = (const float*)d_in[wb + 16];
    const float* mr_b2  = (const float*)d_in[wb + 17];

    float* x = (float*)d_out;

    cudaFuncSetAttribute(mlp_big<0,64>, cudaFuncAttributeMaxDynamicSharedMemorySize, SMEM_B01_64);
    cudaFuncSetAttribute(mlp_big<1,64>, cudaFuncAttributeMaxDynamicSharedMemorySize, SMEM_B01_64);
    cudaFuncSetAttribute(mlp_big<2,64>, cudaFuncAttributeMaxDynamicSharedMemorySize, SMEM_B2_64);
    cudaFuncSetAttribute(mlp_big<0,32>, cudaFuncAttributeMaxDynamicSharedMemorySize, SMEM_B01_32);
    cudaFuncSetAttribute(mlp_big<1,32>, cudaFuncAttributeMaxDynamicSharedMemorySize, SMEM_B01_32);
    cudaFuncSetAttribute(mlp_big<2,32>, cudaFuncAttributeMaxDynamicSharedMemorySize, SMEM_B2_32);
    cudaFuncSetAttribute(mlp_small<1>,  cudaFuncAttributeMaxDynamicSharedMemorySize, SMEM_SMALL);
    cudaFuncSetAttribute(mlp_small<2>,  cudaFuncAttributeMaxDynamicSharedMemorySize, SMEM_SMALL);

    // init: only leaf rows need the original x
    leaf_copy_kernel<<<(NL * 32 + 255) / 256, 256>>>(x, x_in);

    // edge-block layout: block 0 = leaf edges (NL), block d (1..13): 8*(NLEAF>>(d-1)) edges
    int cnt[14], st[14];
    cnt[0] = NL; st[0] = 0;
    for (int d = 1; d < DEPTH; ++d) {
        cnt[d] = 8 * (NLEAF >> (d - 1));
        st[d] = st[d - 1] + cnt[d - 1];
    }

    constexpr int SMALL_THRESH = 2048;

    // ---- nem: leaf -> level-1 ----
    launch_big(0, x, ef, esrc, edst, nullptr,
               nem_w0, nem_b0, nem_w1, nem_b1, nem_w2, nem_b2, 0, 0, NL);

    // ---- mg: upward merge, levels 1..13 (sequential) ----
    for (int d = 1; d < DEPTH; ++d) {
        int half = cnt[d] / 2;
        if (half <= SMALL_THRESH)
            mlp_small<1><<<(half + 15) / 16, 256, SMEM_SMALL>>>(
                x, nullptr, esrc, edst, nullptr,
                mg_w0, mg_b0, mg_w1, mg_b1, mg_w2, mg_b2, st[d], half, half);
        else
            launch_big(1, x, nullptr, esrc, edst, nullptr,
                       mg_w0, mg_b0, mg_w1, mg_b1, mg_w2, mg_b2, st[d], half, half);
    }

    // ---- mr: downward, depth 14..1 (sequential) ----
    for (int depth = DEPTH; depth >= 1; --depth) {
        int sE, m;
        if (depth == 1) { sE = 0; m = NL; }
        else            { sE = st[depth - 1]; m = cnt[depth - 1]; }
        if (m <= SMALL_THRESH)
            mlp_small<2><<<(m + 15) / 16, 256, SMEM_SMALL>>>(
                x, nullptr, esrc, edst, est,
                mr_w0, mr_b0, mr_w1, mr_b1, mr_w2, mr_b2, sE, 0, m);
        else
            launch_big(2, x, nullptr, esrc, edst, est,
                       mr_w0, mr_b0, mr_w1, mr_b1, mr_w2, mr_b2, sE, 0, m);
    }
}

// round 6
// speedup vs baseline: 1.1039x; 1.1039x over previous
#include <cuda_runtime.h>
#include <cstdint>

// Problem constants (shapes fixed by dataset).
constexpr int Hdim   = 128;
constexpr int NLEAF  = 8192;
constexpr int NBATCH = 8;
constexpr int NL     = NBATCH * NLEAF;     // 65536 leaf edges
constexpr int NPT    = 24575;              // nodes per tree
constexpr int NN     = NBATCH * NPT;       // 196600 total nodes
constexpr int DEPTH  = 14;

constexpr int ASTR_BIG   = 260;            // smem stride for 256-wide inputs
constexpr int ASTR_SMALL = 132;            // smem stride for 128/129-wide

constexpr int WCH = 32;                    // weight chunk rows (32x128 = 16KB)

// smem sizes: activations + WCHx128 weight chunk
constexpr int SMEM_B01_64 = (64 * ASTR_BIG   + WCH * Hdim) * 4;  // 82944
constexpr int SMEM_B01_32 = (32 * ASTR_BIG   + WCH * Hdim) * 4;  // 49664
constexpr int SMEM_B2_64  = (64 * ASTR_SMALL + WCH * Hdim) * 4;  // 50176
constexpr int SMEM_B2_32  = (32 * ASTR_SMALL + WCH * Hdim) * 4;  // 33280
constexpr int SMEM_SMALL  = (16 * ASTR_BIG   + WCH * Hdim) * 4;  // 33024

// ---------------- packed fp32x2 helpers (Blackwell FFMA2) ----------------
typedef unsigned long long ull;

#define FMA_F32X2(d, a, b, c) \
    asm("fma.rn.f32x2 %0, %1, %2, %3;" : "=l"(d) : "l"(a), "l"(b), "l"(c))

#define PACK_DUP_F32X2(out, x) \
    asm("mov.b64 %0, {%1, %1};" : "=l"(out) : "r"(__float_as_uint(x)))

#define UNPACK_F32X2(lo, hi, v) \
    asm("mov.b64 {%0, %1}, %2;" : "=f"(lo), "=f"(hi) : "l"(v))

// ======== BIG kernel: TR-row tiles, 128 threads, RPT x 8 per thread ========
// thread grid: 16 col-groups x 8 row-groups; RPT = TR/8.

template<int K, int ASTR, int RPT>
__device__ __forceinline__ void layer_acc2(const float* __restrict__ sA,
                                           float* __restrict__ sW,
                                           const float* __restrict__ w,
                                           int tid, int r0, int c0,
                                           ull (&acc)[RPT][4])
{
#pragma unroll 1
    for (int k0 = 0; k0 < K; k0 += WCH) {
        // stage WCHx128 weight chunk (WCH*32 float4s, 128 threads)
        for (int idx = tid; idx < WCH * 32; idx += 128) {
            reinterpret_cast<float4*>(sW)[idx] =
                reinterpret_cast<const float4*>(w + (size_t)k0 * Hdim)[idx];
        }
        __syncthreads();
#pragma unroll 2
        for (int kq = 0; kq < WCH / 4; ++kq) {
            float4 av[RPT];
#pragma unroll
            for (int i = 0; i < RPT; ++i)
                av[i] = *reinterpret_cast<const float4*>(sA + (r0 + i) * ASTR + k0 + kq * 4);
#pragma unroll
            for (int t = 0; t < 4; ++t) {
                const float* wr = sW + (kq * 4 + t) * Hdim + c0;
                ulonglong2 wA = *reinterpret_cast<const ulonglong2*>(wr);
                ulonglong2 wB = *reinterpret_cast<const ulonglong2*>(wr + 4);
#pragma unroll
                for (int i = 0; i < RPT; ++i) {
                    float a = reinterpret_cast<const float*>(&av[i])[t];
                    ull aa; PACK_DUP_F32X2(aa, a);
                    FMA_F32X2(acc[i][0], aa, wA.x, acc[i][0]);
                    FMA_F32X2(acc[i][1], aa, wA.y, acc[i][1]);
                    FMA_F32X2(acc[i][2], aa, wB.x, acc[i][2]);
                    FMA_F32X2(acc[i][3], aa, wB.y, acc[i][3]);
                }
            }
        }
        __syncthreads();
    }
}

template<int RPT>
__device__ __forceinline__ void zero_acc2(ull (&acc)[RPT][4]) {
#pragma unroll
    for (int i = 0; i < RPT; ++i)
#pragma unroll
        for (int j = 0; j < 4; ++j) acc[i][j] = 0ull;
}

template<int RPT>
__device__ __forceinline__ void epi_bias_relu(ull (&acc)[RPT][4],
                                              const float* __restrict__ b,
                                              float* __restrict__ sA,
                                              int r0, int c0)
{
    float4 bv0 = *reinterpret_cast<const float4*>(b + c0);
    float4 bv1 = *reinterpret_cast<const float4*>(b + c0 + 4);
    const float bv[8] = {bv0.x, bv0.y, bv0.z, bv0.w, bv1.x, bv1.y, bv1.z, bv1.w};
#pragma unroll
    for (int i = 0; i < RPT; ++i) {
        float v[8];
#pragma unroll
        for (int jj = 0; jj < 4; ++jj) {
            float lo, hi; UNPACK_F32X2(lo, hi, acc[i][jj]);
            lo += bv[2 * jj];     hi += bv[2 * jj + 1];
            v[2 * jj]     = lo > 0.f ? lo : 0.f;
            v[2 * jj + 1] = hi > 0.f ? hi : 0.f;
        }
        *reinterpret_cast<float4*>(sA + (r0 + i) * ASTR_SMALL + c0) =
            make_float4(v[0], v[1], v[2], v[3]);
        *reinterpret_cast<float4*>(sA + (r0 + i) * ASTR_SMALL + c0 + 4) =
            make_float4(v[4], v[5], v[6], v[7]);
    }
}

// MODE 0: nem — in=[x[esrc[e]], ef[e]]               (K=256), out -> x[edst[e]]        (set)
// MODE 1: mg  — in=[x[esrc[s+r]], x[esrc[s+half+r]]] (K=256), out -> x[edst[s+half+r]] (set)
// MODE 2: mr  — in=[x[edst[e]], state[e]]            (K=129), out -> x[esrc[e]] += out
template<int MODE, int TR>
__global__ void __launch_bounds__(128, 2)
mlp_big(float* __restrict__ x,
        const float* __restrict__ ef,
        const int* __restrict__ esrc,
        const int* __restrict__ edst,
        const float* __restrict__ est,
        const float* __restrict__ w0, const float* __restrict__ b0,
        const float* __restrict__ w1, const float* __restrict__ b1,
        const float* __restrict__ w2, const float* __restrict__ b2,
        int s, int half, int nrows)
{
    constexpr int RPT   = TR / 8;
    constexpr int ASTR0 = (MODE == 2) ? ASTR_SMALL : ASTR_BIG;
    extern __shared__ float sm[];
    float* sA = sm;
    float* sW = sm + TR * ASTR0;

    const int tid = threadIdx.x;
    const int cx = tid & 15, ry = tid >> 4;      // 16 col-groups x 8 row-groups
    const int c0 = cx * 8, r0 = ry * RPT;
    const int row_base = blockIdx.x * TR;

    // ---- gather inputs into sA ----
    if (MODE == 0 || MODE == 1) {
        for (int idx = tid; idx < TR * 64; idx += 128) {
            int r = idx >> 6, c4 = idx & 63;
            int row = row_base + r;
            if (row < nrows) {
                float4 v;
                if (c4 < 32) {
                    int node = esrc[s + row];
                    v = reinterpret_cast<const float4*>(x + (size_t)node * Hdim)[c4];
                } else if (MODE == 0) {
                    v = reinterpret_cast<const float4*>(ef + (size_t)(s + row) * Hdim)[c4 - 32];
                } else {
                    int node = esrc[s + half + row];
                    v = reinterpret_cast<const float4*>(x + (size_t)node * Hdim)[c4 - 32];
                }
                reinterpret_cast<float4*>(sA + r * ASTR_BIG)[c4] = v;
            }
        }
    } else {
        for (int idx = tid; idx < TR * 32; idx += 128) {
            int r = idx >> 5, c4 = idx & 31;
            int row = row_base + r;
            if (row < nrows) {
                int node = edst[s + row];
                float4 v = reinterpret_cast<const float4*>(x + (size_t)node * Hdim)[c4];
                reinterpret_cast<float4*>(sA + r * ASTR_SMALL)[c4] = v;
            }
        }
        for (int r = tid; r < TR; r += 128) {
            int row = row_base + r;
            sA[r * ASTR_SMALL + 128] = (row < nrows) ? est[s + row] : 0.f;
        }
    }
    __syncthreads();

    ull acc[RPT][4];

    // ---- layer 0 ----
    zero_acc2<RPT>(acc);
    if (MODE == 2) {
        layer_acc2<128, ASTR_SMALL, RPT>(sA, sW, w0, tid, r0, c0, acc);
        // state column: row 128 of w0, straight from global (L2-hot)
        const float* wsr = w0 + (size_t)128 * Hdim + c0;
        ulonglong2 wsA = *reinterpret_cast<const ulonglong2*>(wsr);
        ulonglong2 wsB = *reinterpret_cast<const ulonglong2*>(wsr + 4);
#pragma unroll
        for (int i = 0; i < RPT; ++i) {
            float stv = sA[(r0 + i) * ASTR_SMALL + 128];
            ull aa; PACK_DUP_F32X2(aa, stv);
            FMA_F32X2(acc[i][0], aa, wsA.x, acc[i][0]);
            FMA_F32X2(acc[i][1], aa, wsA.y, acc[i][1]);
            FMA_F32X2(acc[i][2], aa, wsB.x, acc[i][2]);
            FMA_F32X2(acc[i][3], aa, wsB.y, acc[i][3]);
        }
    } else {
        layer_acc2<256, ASTR_BIG, RPT>(sA, sW, w0, tid, r0, c0, acc);
    }
    epi_bias_relu<RPT>(acc, b0, sA, r0, c0);
    __syncthreads();

    // ---- layer 1 ----
    zero_acc2<RPT>(acc);
    layer_acc2<128, ASTR_SMALL, RPT>(sA, sW, w1, tid, r0, c0, acc);
    epi_bias_relu<RPT>(acc, b1, sA, r0, c0);
    __syncthreads();

    // ---- layer 2 + scatter ----
    zero_acc2<RPT>(acc);
    layer_acc2<128, ASTR_SMALL, RPT>(sA, sW, w2, tid, r0, c0, acc);
    {
        float4 bv0 = *reinterpret_cast<const float4*>(b2 + c0);
        float4 bv1 = *reinterpret_cast<const float4*>(b2 + c0 + 4);
        const float bv[8] = {bv0.x, bv0.y, bv0.z, bv0.w, bv1.x, bv1.y, bv1.z, bv1.w};
#pragma unroll
        for (int i = 0; i < RPT; ++i) {
            int row = row_base + r0 + i;
            if (row >= nrows) continue;
            float v[8];
#pragma unroll
            for (int jj = 0; jj < 4; ++jj) {
                float lo, hi; UNPACK_F32X2(lo, hi, acc[i][jj]);
                v[2 * jj]     = lo + bv[2 * jj];
                v[2 * jj + 1] = hi + bv[2 * jj + 1];
            }

            int node;
            if (MODE == 0)      node = edst[s + row];
            else if (MODE == 1) node = edst[s + half + row];
            else                node = esrc[s + row];

            float* p = x + (size_t)node * Hdim + c0;
            if (MODE == 2) {
                float4 o0 = *reinterpret_cast<const float4*>(p);
                float4 o1 = *reinterpret_cast<const float4*>(p + 4);
                v[0] += o0.x; v[1] += o0.y; v[2] += o0.z; v[3] += o0.w;
                v[4] += o1.x; v[5] += o1.y; v[6] += o1.z; v[7] += o1.w;
            }
            *reinterpret_cast<float4*>(p)     = make_float4(v[0], v[1], v[2], v[3]);
            *reinterpret_cast<float4*>(p + 4) = make_float4(v[4], v[5], v[6], v[7]);
        }
    }
}

// =============== SMALL kernel: 16-row tiles, 256 threads, 1x8/thread =======

template<int K, int ASTR>
__device__ __forceinline__ void layer_acc_s(const float* __restrict__ sA,
                                            float* __restrict__ sW,
                                            const float* __restrict__ w,
                                            int tid, int r0, int c0,
                                            float (&acc)[8])
{
#pragma unroll 1
    for (int k0 = 0; k0 < K; k0 += WCH) {
        for (int idx = tid; idx < WCH * 32; idx += 256) {
            reinterpret_cast<float4*>(sW)[idx] =
                reinterpret_cast<const float4*>(w + (size_t)k0 * Hdim)[idx];
        }
        __syncthreads();
#pragma unroll 4
        for (int kq = 0; kq < WCH / 4; ++kq) {
            float4 av = *reinterpret_cast<const float4*>(sA + r0 * ASTR + k0 + kq * 4);
#pragma unroll
            for (int t = 0; t < 4; ++t) {
                const float* wr = sW + (kq * 4 + t) * Hdim + c0;
                float4 w0v = *reinterpret_cast<const float4*>(wr);
                float4 w1v = *reinterpret_cast<const float4*>(wr + 4);
                float a = reinterpret_cast<const float*>(&av)[t];
                acc[0] = fmaf(a, w0v.x, acc[0]);
                acc[1] = fmaf(a, w0v.y, acc[1]);
                acc[2] = fmaf(a, w0v.z, acc[2]);
                acc[3] = fmaf(a, w0v.w, acc[3]);
                acc[4] = fmaf(a, w1v.x, acc[4]);
                acc[5] = fmaf(a, w1v.y, acc[5]);
                acc[6] = fmaf(a, w1v.z, acc[6]);
                acc[7] = fmaf(a, w1v.w, acc[7]);
            }
        }
        __syncthreads();
    }
}

template<int MODE>
__global__ void __launch_bounds__(256)
mlp_small(float* __restrict__ x,
          const float* __restrict__ ef,
          const int* __restrict__ esrc,
          const int* __restrict__ edst,
          const float* __restrict__ est,
          const float* __restrict__ w0, const float* __restrict__ b0,
          const float* __restrict__ w1, const float* __restrict__ b1,
          const float* __restrict__ w2, const float* __restrict__ b2,
          int s, int half, int nrows)
{
    extern __shared__ float sm[];
    float* sA = sm;
    float* sW = sm + 16 * ASTR_BIG;

    const int tid = threadIdx.x;
    const int cx = tid & 15, ry = tid >> 4;      // 16 col-groups x 16 rows
    const int c0 = cx * 8, r0 = ry;
    const int row_base = blockIdx.x * 16;

    if (MODE == 0 || MODE == 1) {
        for (int idx = tid; idx < 16 * 64; idx += 256) {
            int r = idx >> 6, c4 = idx & 63;
            int row = row_base + r;
            if (row < nrows) {
                float4 v;
                if (c4 < 32) {
                    int node = esrc[s + row];
                    v = reinterpret_cast<const float4*>(x + (size_t)node * Hdim)[c4];
                } else if (MODE == 0) {
                    v = reinterpret_cast<const float4*>(ef + (size_t)(s + row) * Hdim)[c4 - 32];
                } else {
                    int node = esrc[s + half + row];
                    v = reinterpret_cast<const float4*>(x + (size_t)node * Hdim)[c4 - 32];
                }
                reinterpret_cast<float4*>(sA + r * ASTR_BIG)[c4] = v;
            }
        }
    } else {
        for (int idx = tid; idx < 16 * 32; idx += 256) {
            int r = idx >> 5, c4 = idx & 31;
            int row = row_base + r;
            if (row < nrows) {
                int node = edst[s + row];
                float4 v = reinterpret_cast<const float4*>(x + (size_t)node * Hdim)[c4];
                reinterpret_cast<float4*>(sA + r * ASTR_SMALL)[c4] = v;
            }
        }
        for (int r = tid; r < 16; r += 256) {
            int row = row_base + r;
            sA[r * ASTR_SMALL + 128] = (row < nrows) ? est[s + row] : 0.f;
        }
    }
    __syncthreads();

    float acc[8];

    // ---- layer 0 ----
#pragma unroll
    for (int j = 0; j < 8; ++j) acc[j] = 0.f;
    if (MODE == 2) {
        layer_acc_s<128, ASTR_SMALL>(sA, sW, w0, tid, r0, c0, acc);
        const float* wsr = w0 + (size_t)128 * Hdim + c0;
        float stv = sA[r0 * ASTR_SMALL + 128];
#pragma unroll
        for (int j = 0; j < 8; ++j) acc[j] = fmaf(stv, wsr[j], acc[j]);
    } else {
        layer_acc_s<256, ASTR_BIG>(sA, sW, w0, tid, r0, c0, acc);
    }
    {
#pragma unroll
        for (int j = 0; j < 8; ++j) {
            float v = acc[j] + b0[c0 + j];
            acc[j] = v > 0.f ? v : 0.f;
        }
        *reinterpret_cast<float4*>(sA + r0 * ASTR_SMALL + c0) =
            make_float4(acc[0], acc[1], acc[2], acc[3]);
        *reinterpret_cast<float4*>(sA + r0 * ASTR_SMALL + c0 + 4) =
            make_float4(acc[4], acc[5], acc[6], acc[7]);
    }
    __syncthreads();

    // ---- layer 1 ----
#pragma unroll
    for (int j = 0; j < 8; ++j) acc[j] = 0.f;
    layer_acc_s<128, ASTR_SMALL>(sA, sW, w1, tid, r0, c0, acc);
    {
#pragma unroll
        for (int j = 0; j < 8; ++j) {
            float v = acc[j] + b1[c0 + j];
            acc[j] = v > 0.f ? v : 0.f;
        }
        *reinterpret_cast<float4*>(sA + r0 * ASTR_SMALL + c0) =
            make_float4(acc[0], acc[1], acc[2], acc[3]);
        *reinterpret_cast<float4*>(sA + r0 * ASTR_SMALL + c0 + 4) =
            make_float4(acc[4], acc[5], acc[6], acc[7]);
    }
    __syncthreads();

    // ---- layer 2 + scatter ----
#pragma unroll
    for (int j = 0; j < 8; ++j) acc[j] = 0.f;
    layer_acc_s<128, ASTR_SMALL>(sA, sW, w2, tid, r0, c0, acc);
    {
        int row = row_base + r0;
        if (row < nrows) {
#pragma unroll
            for (int j = 0; j < 8; ++j) acc[j] += b2[c0 + j];

            int node;
            if (MODE == 0)      node = edst[s + row];
            else if (MODE == 1) node = edst[s + half + row];
            else                node = esrc[s + row];

            float* p = x + (size_t)node * Hdim + c0;
            if (MODE == 2) {
                float4 o0 = *reinterpret_cast<const float4*>(p);
                float4 o1 = *reinterpret_cast<const float4*>(p + 4);
                acc[0] += o0.x; acc[1] += o0.y; acc[2] += o0.z; acc[3] += o0.w;
                acc[4] += o1.x; acc[5] += o1.y; acc[6] += o1.z; acc[7] += o1.w;
            }
            *reinterpret_cast<float4*>(p)     = make_float4(acc[0], acc[1], acc[2], acc[3]);
            *reinterpret_cast<float4*>(p + 4) = make_float4(acc[4], acc[5], acc[6], acc[7]);
        }
    }
}

// copy only leaf rows of x (everything else is provably overwritten)
__global__ void leaf_copy_kernel(float* __restrict__ x, const float* __restrict__ x_in)
{
    int idx = blockIdx.x * blockDim.x + threadIdx.x;   // over NL*32 float4s
    if (idx >= NL * 32) return;
    int r = idx >> 5, c4 = idx & 31;
    int b = r >> 13, leaf = r & (NLEAF - 1);
    size_t node = (size_t)b * NPT + leaf;
    reinterpret_cast<float4*>(x + node * Hdim)[c4] =
        reinterpret_cast<const float4*>(x_in + node * Hdim)[c4];
}

// ---------------- dispatch helpers ----------------
static inline void launch_big(int MODE, float* x, const float* ef,
                              const int* esrc, const int* edst, const float* est,
                              const float* w0, const float* b0,
                              const float* w1, const float* b1,
                              const float* w2, const float* b2,
                              int s, int half, int nrows)
{
    bool tr32 = (nrows <= 9472);
    if (MODE == 0) {
        if (tr32) mlp_big<0,32><<<(nrows + 31) / 32, 128, SMEM_B01_32>>>(x, ef, esrc, edst, est, w0, b0, w1, b1, w2, b2, s, half, nrows);
        else      mlp_big<0,64><<<(nrows + 63) / 64, 128, SMEM_B01_64>>>(x, ef, esrc, edst, est, w0, b0, w1, b1, w2, b2, s, half, nrows);
    } else if (MODE == 1) {
        if (tr32) mlp_big<1,32><<<(nrows + 31) / 32, 128, SMEM_B01_32>>>(x, ef, esrc, edst, est, w0, b0, w1, b1, w2, b2, s, half, nrows);
        else      mlp_big<1,64><<<(nrows + 63) / 64, 128, SMEM_B01_64>>>(x, ef, esrc, edst, est, w0, b0, w1, b1, w2, b2, s, half, nrows);
    } else {
        if (tr32) mlp_big<2,32><<<(nrows + 31) / 32, 128, SMEM_B2_32>>>(x, ef, esrc, edst, est, w0, b0, w1, b1, w2, b2, s, half, nrows);
        else      mlp_big<2,64><<<(nrows + 63) / 64, 128, SMEM_B2_64>>>(x, ef, esrc, edst, est, w0, b0, w1, b1, w2, b2, s, half, nrows);
    }
}

template<typename F>
static inline void set_attrs(F f, int smem) {
    cudaFuncSetAttribute(f, cudaFuncAttributeMaxDynamicSharedMemorySize, smem);
    cudaFuncSetAttribute(f, cudaFuncAttributePreferredSharedMemoryCarveout, 100);
}

extern "C" void kernel_launch(void* const* d_in, const int* in_sizes, int n_in,
                              void* d_out, int out_size)
{
    (void)n_in; (void)out_size;

    const float* x_in = (const float*)d_in[0];
    const int*   esrc = (const int*)  d_in[1];
    const int*   edst = (const int*)  d_in[2];
    const float* est  = (const float*)d_in[3];
    const float* ef   = (const float*)d_in[4];

    int wb = (in_sizes[5] == 1) ? 6 : 5;   // input 5 = scalar gcmn_depth

    const float* nem_w0 = (const float*)d_in[wb + 0];
    const float* nem_b0 = (const float*)d_in[wb + 1];
    const float* nem_w1 = (const float*)d_in[wb + 2];
    const float* nem_b1 = (const float*)d_in[wb + 3];
    const float* nem_w2 = (const float*)d_in[wb + 4];
    const float* nem_b2 = (const float*)d_in[wb + 5];
    const float* mg_w0  = (const float*)d_in[wb + 6];
    const float* mg_b0  = (const float*)d_in[wb + 7];
    const float* mg_w1  = (const float*)d_in[wb + 8];
    const float* mg_b1  = (const float*)d_in[wb + 9];
    const float* mg_w2  = (const float*)d_in[wb + 10];
    const float* mg_b2  = (const float*)d_in[wb + 11];
    const float* mr_w0  = (const float*)d_in[wb + 12];
    const float* mr_b0  = (const float*)d_in[wb + 13];
    const float* mr_w1  = (const float*)d_in[wb + 14];
    const float* mr_b1  = (const float*)d_in[wb + 15];
    const float* mr_w2  = (const float*)d_in[wb + 16];
    const float* mr_b2  = (const float*)d_in[wb + 17];

    float* x = (float*)d_out;

    set_attrs(mlp_big<0,64>, SMEM_B01_64);
    set_attrs(mlp_big<1,64>, SMEM_B01_64);
    set_attrs(mlp_big<2,64>, SMEM_B2_64);
    set_attrs(mlp_big<0,32>, SMEM_B01_32);
    set_attrs(mlp_big<1,32>, SMEM_B01_32);
    set_attrs(mlp_big<2,32>, SMEM_B2_32);
    set_attrs(mlp_small<1>,  SMEM_SMALL);
    set_attrs(mlp_small<2>,  SMEM_SMALL);

    // init: only leaf rows need the original x
    leaf_copy_kernel<<<(NL * 32 + 255) / 256, 256>>>(x, x_in);

    // edge-block layout: block 0 = leaf edges (NL), block d (1..13): 8*(NLEAF>>(d-1)) edges
    int cnt[14], st[14];
    cnt[0] = NL; st[0] = 0;
    for (int d = 1; d < DEPTH; ++d) {
        cnt[d] = 8 * (NLEAF >> (d - 1));
        st[d] = st[d - 1] + cnt[d - 1];
    }

    constexpr int SMALL_THRESH = 2048;

    // ---- nem: leaf -> level-1 ----
    launch_big(0, x, ef, esrc, edst, nullptr,
               nem_w0, nem_b0, nem_w1, nem_b1, nem_w2, nem_b2, 0, 0, NL);

    // ---- mg: upward merge, levels 1..13 (sequential) ----
    for (int d = 1; d < DEPTH; ++d) {
        int half = cnt[d] / 2;
        if (half <= SMALL_THRESH)
            mlp_small<1><<<(half + 15) / 16, 256, SMEM_SMALL>>>(
                x, nullptr, esrc, edst, nullptr,
                mg_w0, mg_b0, mg_w1, mg_b1, mg_w2, mg_b2, st[d], half, half);
        else
            launch_big(1, x, nullptr, esrc, edst, nullptr,
                       mg_w0, mg_b0, mg_w1, mg_b1, mg_w2, mg_b2, st[d], half, half);
    }

    // ---- mr: downward, depth 14..1 (sequential) ----
    for (int depth = DEPTH; depth >= 1; --depth) {
        int sE, m;
        if (depth == 1) { sE = 0; m = NL; }
        else            { sE = st[depth - 1]; m = cnt[depth - 1]; }
        if (m <= SMALL_THRESH)
            mlp_small<2><<<(m + 15) / 16, 256, SMEM_SMALL>>>(
                x, nullptr, esrc, edst, est,
                mr_w0, mr_b0, mr_w1, mr_b1, mr_w2, mr_b2, sE, 0, m);
        else
            launch_big(2, x, nullptr, esrc, edst, est,
                       mr_w0, mr_b0, mr_w1, mr_b1, mr_w2, mr_b2, sE, 0, m);
    }
}

// round 7
// speedup vs baseline: 1.1537x; 1.0452x over previous
#include <cuda_runtime.h>
#include <cstdint>

// Problem constants (shapes fixed by dataset).
constexpr int Hdim   = 128;
constexpr int NLEAF  = 8192;
constexpr int NBATCH = 8;
constexpr int NL     = NBATCH * NLEAF;     // 65536 leaf edges
constexpr int NPT    = 24575;              // nodes per tree
constexpr int NN     = NBATCH * NPT;       // 196600 total nodes
constexpr int DEPTH  = 14;

constexpr int ASTR_BIG   = 260;            // smem stride for 256-wide inputs
constexpr int ASTR_SMALL = 132;            // smem stride for 128/129-wide
constexpr int SWSTR      = 132;            // weight smem stride

// MMA kernel smem: sA + sW_hi + sW_lo (64x128 chunk each)
constexpr int SMEM_MMA_01 = (64 * ASTR_BIG   + 2 * 64 * SWSTR) * 4;  // 134144
constexpr int SMEM_MMA_2  = (64 * ASTR_SMALL + 2 * 64 * SWSTR) * 4;  // 101376
// small scalar kernel smem
constexpr int WCH_S = 32;
constexpr int SMEM_SMALL  = (16 * ASTR_BIG + WCH_S * Hdim) * 4;      // 33024

// ---------------- tf32 helpers ----------------
#define CVT_TF32(d, s) asm("cvt.rna.tf32.f32 %0, %1;" : "=r"(d) : "f"(s))

__device__ __forceinline__ void split_tf32(float v, uint32_t& hi, uint32_t& lo) {
    CVT_TF32(hi, v);
    float r = v - __uint_as_float(hi);
    CVT_TF32(lo, r);
}

__device__ __forceinline__ void mma_tf32(float (&c)[4], const uint32_t (&a)[4],
                                         uint32_t b0, uint32_t b1) {
    asm volatile(
        "mma.sync.aligned.m16n8k8.row.col.f32.tf32.tf32.f32 "
        "{%0,%1,%2,%3}, {%4,%5,%6,%7}, {%8,%9}, {%0,%1,%2,%3};"
        : "+f"(c[0]), "+f"(c[1]), "+f"(c[2]), "+f"(c[3])
        : "r"(a[0]), "r"(a[1]), "r"(a[2]), "r"(a[3]), "r"(b0), "r"(b1));
}

// ---- one MLP layer via 3xTF32 mma. K multiple of 64. ----
// Warp owns 32 rows x 32 cols: 2 m-tiles x 4 n-tiles of m16n8k8.
template<int K, int ASTR>
__device__ __forceinline__ void layer_mma(const float* __restrict__ sA,
                                          float* __restrict__ sWh,
                                          float* __restrict__ sWl,
                                          const float* __restrict__ w,
                                          int tid, int mrow0, int ncol0,
                                          int qr, int qc,
                                          float (&C)[2][4][4])
{
#pragma unroll 1
    for (int k0 = 0; k0 < K; k0 += 64) {
        // stage + hi/lo split a 64x128 weight chunk
        for (int idx = tid; idx < 64 * 32; idx += 256) {
            int kr = idx >> 5, c4 = idx & 31;
            float4 v = reinterpret_cast<const float4*>(w + (size_t)(k0 + kr) * Hdim)[c4];
            uint32_t h, l;
            float4 hv, lv;
            split_tf32(v.x, h, l); hv.x = __uint_as_float(h); lv.x = __uint_as_float(l);
            split_tf32(v.y, h, l); hv.y = __uint_as_float(h); lv.y = __uint_as_float(l);
            split_tf32(v.z, h, l); hv.z = __uint_as_float(h); lv.z = __uint_as_float(l);
            split_tf32(v.w, h, l); hv.w = __uint_as_float(h); lv.w = __uint_as_float(l);
            *reinterpret_cast<float4*>(sWh + kr * SWSTR + c4 * 4) = hv;
            *reinterpret_cast<float4*>(sWl + kr * SWSTR + c4 * 4) = lv;
        }
        __syncthreads();
#pragma unroll 2
        for (int ks = 0; ks < 8; ++ks) {
            const int kc = k0 + ks * 8 + qc;
            uint32_t Ah[2][4], Al[2][4];
#pragma unroll
            for (int mt = 0; mt < 2; ++mt) {
                int rb = mrow0 + 16 * mt;
                float x0 = sA[(rb + qr    ) * ASTR + kc    ];
                float x1 = sA[(rb + qr + 8) * ASTR + kc    ];
                float x2 = sA[(rb + qr    ) * ASTR + kc + 4];
                float x3 = sA[(rb + qr + 8) * ASTR + kc + 4];
                split_tf32(x0, Ah[mt][0], Al[mt][0]);
                split_tf32(x1, Ah[mt][1], Al[mt][1]);
                split_tf32(x2, Ah[mt][2], Al[mt][2]);
                split_tf32(x3, Ah[mt][3], Al[mt][3]);
            }
            const int krow = ks * 8 + qc;
#pragma unroll
            for (int nt = 0; nt < 4; ++nt) {
                int nb = ncol0 + 8 * nt + qr;
                uint32_t bh0 = __float_as_uint(sWh[(krow    ) * SWSTR + nb]);
                uint32_t bh1 = __float_as_uint(sWh[(krow + 4) * SWSTR + nb]);
                uint32_t bl0 = __float_as_uint(sWl[(krow    ) * SWSTR + nb]);
                uint32_t bl1 = __float_as_uint(sWl[(krow + 4) * SWSTR + nb]);
#pragma unroll
                for (int mt = 0; mt < 2; ++mt) {
                    mma_tf32(C[mt][nt], Ah[mt], bl0, bl1);   // hi*lo
                    mma_tf32(C[mt][nt], Al[mt], bh0, bh1);   // lo*hi
                    mma_tf32(C[mt][nt], Ah[mt], bh0, bh1);   // hi*hi
                }
            }
        }
        __syncthreads();
    }
}

__device__ __forceinline__ void zero_C(float (&C)[2][4][4]) {
#pragma unroll
    for (int mt = 0; mt < 2; ++mt)
#pragma unroll
        for (int nt = 0; nt < 4; ++nt)
#pragma unroll
            for (int j = 0; j < 4; ++j) C[mt][nt][j] = 0.f;
}

template<bool RELU>
__device__ __forceinline__ void epi_store(float (&C)[2][4][4],
                                          const float* __restrict__ b,
                                          float* __restrict__ sA,
                                          int mrow0, int ncol0, int qr, int qc)
{
#pragma unroll
    for (int mt = 0; mt < 2; ++mt) {
        int rb = mrow0 + 16 * mt + qr;
#pragma unroll
        for (int nt = 0; nt < 4; ++nt) {
            int nb = ncol0 + 8 * nt + 2 * qc;
            float2 bv = *reinterpret_cast<const float2*>(b + nb);
            float v0 = C[mt][nt][0] + bv.x, v1 = C[mt][nt][1] + bv.y;
            float v2 = C[mt][nt][2] + bv.x, v3 = C[mt][nt][3] + bv.y;
            if (RELU) {
                v0 = v0 > 0.f ? v0 : 0.f;  v1 = v1 > 0.f ? v1 : 0.f;
                v2 = v2 > 0.f ? v2 : 0.f;  v3 = v3 > 0.f ? v3 : 0.f;
            }
            *reinterpret_cast<float2*>(sA + rb * ASTR_SMALL + nb)       = make_float2(v0, v1);
            *reinterpret_cast<float2*>(sA + (rb + 8) * ASTR_SMALL + nb) = make_float2(v2, v3);
        }
    }
}

// MODE 0: nem — in=[x[esrc[e]], ef[e]]               (K=256), out -> x[edst[e]]        (set)
// MODE 1: mg  — in=[x[esrc[s+r]], x[esrc[s+half+r]]] (K=256), out -> x[edst[s+half+r]] (set)
// MODE 2: mr  — in=[x[edst[e]], state[e]]            (K=129), out -> x[esrc[e]] += out
template<int MODE>
__global__ void __launch_bounds__(256, 1)
mlp_mma(float* __restrict__ x,
        const float* __restrict__ ef,
        const int* __restrict__ esrc,
        const int* __restrict__ edst,
        const float* __restrict__ est,
        const float* __restrict__ w0, const float* __restrict__ b0,
        const float* __restrict__ w1, const float* __restrict__ b1,
        const float* __restrict__ w2, const float* __restrict__ b2,
        int s, int half, int nrows)
{
    constexpr int ASTR0 = (MODE == 2) ? ASTR_SMALL : ASTR_BIG;
    extern __shared__ float sm[];
    float* sA  = sm;
    float* sWh = sm + 64 * ASTR0;
    float* sWl = sWh + 64 * SWSTR;

    const int tid  = threadIdx.x;
    const int wid  = tid >> 5, lane = tid & 31;
    const int qr   = lane >> 2, qc = lane & 3;
    const int mrow0 = (wid >> 2) * 32;       // warp row block (0 or 32)
    const int ncol0 = (wid & 3) * 32;        // warp col block (0,32,64,96)
    const int row_base = blockIdx.x * 64;

    // ---- gather inputs into sA ----
    if (MODE == 0 || MODE == 1) {
        for (int idx = tid; idx < 64 * 64; idx += 256) {
            int r = idx >> 6, c4 = idx & 63;
            int row = row_base + r;
            if (row < nrows) {
                float4 v;
                if (c4 < 32) {
                    int node = esrc[s + row];
                    v = reinterpret_cast<const float4*>(x + (size_t)node * Hdim)[c4];
                } else if (MODE == 0) {
                    v = reinterpret_cast<const float4*>(ef + (size_t)(s + row) * Hdim)[c4 - 32];
                } else {
                    int node = esrc[s + half + row];
                    v = reinterpret_cast<const float4*>(x + (size_t)node * Hdim)[c4 - 32];
                }
                reinterpret_cast<float4*>(sA + r * ASTR_BIG)[c4] = v;
            }
        }
    } else {
        for (int idx = tid; idx < 64 * 32; idx += 256) {
            int r = idx >> 5, c4 = idx & 31;
            int row = row_base + r;
            if (row < nrows) {
                int node = edst[s + row];
                float4 v = reinterpret_cast<const float4*>(x + (size_t)node * Hdim)[c4];
                reinterpret_cast<float4*>(sA + r * ASTR_SMALL)[c4] = v;
            }
        }
        for (int r = tid; r < 64; r += 256) {
            int row = row_base + r;
            sA[r * ASTR_SMALL + 128] = (row < nrows) ? est[s + row] : 0.f;
        }
    }
    __syncthreads();

    float C[2][4][4];

    // ---- layer 0 ----
    zero_C(C);
    if (MODE == 2) {
        layer_mma<128, ASTR_SMALL>(sA, sWh, sWl, w0, tid, mrow0, ncol0, qr, qc, C);
        // state column: row 128 of w0 (scalar fp32, exact)
#pragma unroll
        for (int mt = 0; mt < 2; ++mt) {
            int rb = mrow0 + 16 * mt + qr;
            float st0 = sA[rb * ASTR_SMALL + 128];
            float st1 = sA[(rb + 8) * ASTR_SMALL + 128];
#pragma unroll
            for (int nt = 0; nt < 4; ++nt) {
                int nb = ncol0 + 8 * nt + 2 * qc;
                float2 wsv = *reinterpret_cast<const float2*>(w0 + (size_t)128 * Hdim + nb);
                C[mt][nt][0] = fmaf(st0, wsv.x, C[mt][nt][0]);
                C[mt][nt][1] = fmaf(st0, wsv.y, C[mt][nt][1]);
                C[mt][nt][2] = fmaf(st1, wsv.x, C[mt][nt][2]);
                C[mt][nt][3] = fmaf(st1, wsv.y, C[mt][nt][3]);
            }
        }
    } else {
        layer_mma<256, ASTR_BIG>(sA, sWh, sWl, w0, tid, mrow0, ncol0, qr, qc, C);
    }
    epi_store<true>(C, b0, sA, mrow0, ncol0, qr, qc);
    __syncthreads();

    // ---- layer 1 ----
    zero_C(C);
    layer_mma<128, ASTR_SMALL>(sA, sWh, sWl, w1, tid, mrow0, ncol0, qr, qc, C);
    epi_store<true>(C, b1, sA, mrow0, ncol0, qr, qc);
    __syncthreads();

    // ---- layer 2 (no relu) ----
    zero_C(C);
    layer_mma<128, ASTR_SMALL>(sA, sWh, sWl, w2, tid, mrow0, ncol0, qr, qc, C);
    epi_store<false>(C, b2, sA, mrow0, ncol0, qr, qc);
    __syncthreads();

    // ---- scatter from sA ----
    for (int idx = tid; idx < 64 * 32; idx += 256) {
        int r = idx >> 5, c4 = idx & 31;
        int row = row_base + r;
        if (row < nrows) {
            int node;
            if (MODE == 0)      node = edst[s + row];
            else if (MODE == 1) node = edst[s + half + row];
            else                node = esrc[s + row];
            float4 v = *reinterpret_cast<const float4*>(sA + r * ASTR_SMALL + c4 * 4);
            float* p = x + (size_t)node * Hdim + c4 * 4;
            if (MODE == 2) {
                float4 o = *reinterpret_cast<const float4*>(p);
                v.x += o.x; v.y += o.y; v.z += o.z; v.w += o.w;
            }
            *reinterpret_cast<float4*>(p) = v;
        }
    }
}

// =============== SMALL kernel: 16-row tiles, 256 threads, 1x8/thread (scalar) ====

template<int K, int ASTR>
__device__ __forceinline__ void layer_acc_s(const float* __restrict__ sA,
                                            float* __restrict__ sW,
                                            const float* __restrict__ w,
                                            int tid, int r0, int c0,
                                            float (&acc)[8])
{
#pragma unroll 1
    for (int k0 = 0; k0 < K; k0 += WCH_S) {
        for (int idx = tid; idx < WCH_S * 32; idx += 256) {
            reinterpret_cast<float4*>(sW)[idx] =
                reinterpret_cast<const float4*>(w + (size_t)k0 * Hdim)[idx];
        }
        __syncthreads();
#pragma unroll 4
        for (int kq = 0; kq < WCH_S / 4; ++kq) {
            float4 av = *reinterpret_cast<const float4*>(sA + r0 * ASTR + k0 + kq * 4);
#pragma unroll
            for (int t = 0; t < 4; ++t) {
                const float* wr = sW + (kq * 4 + t) * Hdim + c0;
                float4 w0v = *reinterpret_cast<const float4*>(wr);
                float4 w1v = *reinterpret_cast<const float4*>(wr + 4);
                float a = reinterpret_cast<const float*>(&av)[t];
                acc[0] = fmaf(a, w0v.x, acc[0]);
                acc[1] = fmaf(a, w0v.y, acc[1]);
                acc[2] = fmaf(a, w0v.z, acc[2]);
                acc[3] = fmaf(a, w0v.w, acc[3]);
                acc[4] = fmaf(a, w1v.x, acc[4]);
                acc[5] = fmaf(a, w1v.y, acc[5]);
                acc[6] = fmaf(a, w1v.z, acc[6]);
                acc[7] = fmaf(a, w1v.w, acc[7]);
            }
        }
        __syncthreads();
    }
}

template<int MODE>
__global__ void __launch_bounds__(256)
mlp_small(float* __restrict__ x,
          const float* __restrict__ ef,
          const int* __restrict__ esrc,
          const int* __restrict__ edst,
          const float* __restrict__ est,
          const float* __restrict__ w0, const float* __restrict__ b0,
          const float* __restrict__ w1, const float* __restrict__ b1,
          const float* __restrict__ w2, const float* __restrict__ b2,
          int s, int half, int nrows)
{
    extern __shared__ float sm[];
    float* sA = sm;
    float* sW = sm + 16 * ASTR_BIG;

    const int tid = threadIdx.x;
    const int cx = tid & 15, ry = tid >> 4;
    const int c0 = cx * 8, r0 = ry;
    const int row_base = blockIdx.x * 16;

    if (MODE == 0 || MODE == 1) {
        for (int idx = tid; idx < 16 * 64; idx += 256) {
            int r = idx >> 6, c4 = idx & 63;
            int row = row_base + r;
            if (row < nrows) {
                float4 v;
                if (c4 < 32) {
                    int node = esrc[s + row];
                    v = reinterpret_cast<const float4*>(x + (size_t)node * Hdim)[c4];
                } else if (MODE == 0) {
                    v = reinterpret_cast<const float4*>(ef + (size_t)(s + row) * Hdim)[c4 - 32];
                } else {
                    int node = esrc[s + half + row];
                    v = reinterpret_cast<const float4*>(x + (size_t)node * Hdim)[c4 - 32];
                }
                reinterpret_cast<float4*>(sA + r * ASTR_BIG)[c4] = v;
            }
        }
    } else {
        for (int idx = tid; idx < 16 * 32; idx += 256) {
            int r = idx >> 5, c4 = idx & 31;
            int row = row_base + r;
            if (row < nrows) {
                int node = edst[s + row];
                float4 v = reinterpret_cast<const float4*>(x + (size_t)node * Hdim)[c4];
                reinterpret_cast<float4*>(sA + r * ASTR_SMALL)[c4] = v;
            }
        }
        for (int r = tid; r < 16; r += 256) {
            int row = row_base + r;
            sA[r * ASTR_SMALL + 128] = (row < nrows) ? est[s + row] : 0.f;
        }
    }
    __syncthreads();

    float acc[8];

#pragma unroll
    for (int j = 0; j < 8; ++j) acc[j] = 0.f;
    if (MODE == 2) {
        layer_acc_s<128, ASTR_SMALL>(sA, sW, w0, tid, r0, c0, acc);
        const float* wsr = w0 + (size_t)128 * Hdim + c0;
        float stv = sA[r0 * ASTR_SMALL + 128];
#pragma unroll
        for (int j = 0; j < 8; ++j) acc[j] = fmaf(stv, wsr[j], acc[j]);
    } else {
        layer_acc_s<256, ASTR_BIG>(sA, sW, w0, tid, r0, c0, acc);
    }
    {
#pragma unroll
        for (int j = 0; j < 8; ++j) {
            float v = acc[j] + b0[c0 + j];
            acc[j] = v > 0.f ? v : 0.f;
        }
        *reinterpret_cast<float4*>(sA + r0 * ASTR_SMALL + c0) =
            make_float4(acc[0], acc[1], acc[2], acc[3]);
        *reinterpret_cast<float4*>(sA + r0 * ASTR_SMALL + c0 + 4) =
            make_float4(acc[4], acc[5], acc[6], acc[7]);
    }
    __syncthreads();

#pragma unroll
    for (int j = 0; j < 8; ++j) acc[j] = 0.f;
    layer_acc_s<128, ASTR_SMALL>(sA, sW, w1, tid, r0, c0, acc);
    {
#pragma unroll
        for (int j = 0; j < 8; ++j) {
            float v = acc[j] + b1[c0 + j];
            acc[j] = v > 0.f ? v : 0.f;
        }
        *reinterpret_cast<float4*>(sA + r0 * ASTR_SMALL + c0) =
            make_float4(acc[0], acc[1], acc[2], acc[3]);
        *reinterpret_cast<float4*>(sA + r0 * ASTR_SMALL + c0 + 4) =
            make_float4(acc[4], acc[5], acc[6], acc[7]);
    }
    __syncthreads();

#pragma unroll
    for (int j = 0; j < 8; ++j) acc[j] = 0.f;
    layer_acc_s<128, ASTR_SMALL>(sA, sW, w2, tid, r0, c0, acc);
    {
        int row = row_base + r0;
        if (row < nrows) {
#pragma unroll
            for (int j = 0; j < 8; ++j) acc[j] += b2[c0 + j];

            int node;
            if (MODE == 0)      node = edst[s + row];
            else if (MODE == 1) node = edst[s + half + row];
            else                node = esrc[s + row];

            float* p = x + (size_t)node * Hdim + c0;
            if (MODE == 2) {
                float4 o0 = *reinterpret_cast<const float4*>(p);
                float4 o1 = *reinterpret_cast<const float4*>(p + 4);
                acc[0] += o0.x; acc[1] += o0.y; acc[2] += o0.z; acc[3] += o0.w;
                acc[4] += o1.x; acc[5] += o1.y; acc[6] += o1.z; acc[7] += o1.w;
            }
            *reinterpret_cast<float4*>(p)     = make_float4(acc[0], acc[1], acc[2], acc[3]);
            *reinterpret_cast<float4*>(p + 4) = make_float4(acc[4], acc[5], acc[6], acc[7]);
        }
    }
}

// copy only leaf rows of x (everything else is provably overwritten)
__global__ void leaf_copy_kernel(float* __restrict__ x, const float* __restrict__ x_in)
{
    int idx = blockIdx.x * blockDim.x + threadIdx.x;   // over NL*32 float4s
    if (idx >= NL * 32) return;
    int r = idx >> 5, c4 = idx & 31;
    int b = r >> 13, leaf = r & (NLEAF - 1);
    size_t node = (size_t)b * NPT + leaf;
    reinterpret_cast<float4*>(x + node * Hdim)[c4] =
        reinterpret_cast<const float4*>(x_in + node * Hdim)[c4];
}

extern "C" void kernel_launch(void* const* d_in, const int* in_sizes, int n_in,
                              void* d_out, int out_size)
{
    (void)n_in; (void)out_size;

    const float* x_in = (const float*)d_in[0];
    const int*   esrc = (const int*)  d_in[1];
    const int*   edst = (const int*)  d_in[2];
    const float* est  = (const float*)d_in[3];
    const float* ef   = (const float*)d_in[4];

    int wb = (in_sizes[5] == 1) ? 6 : 5;   // input 5 = scalar gcmn_depth

    const float* nem_w0 = (const float*)d_in[wb + 0];
    const float* nem_b0 = (const float*)d_in[wb + 1];
    const float* nem_w1 = (const float*)d_in[wb + 2];
    const float* nem_b1 = (const float*)d_in[wb + 3];
    const float* nem_w2 = (const float*)d_in[wb + 4];
    const float* nem_b2 = (const float*)d_in[wb + 5];
    const float* mg_w0  = (const float*)d_in[wb + 6];
    const float* mg_b0  = (const float*)d_in[wb + 7];
    const float* mg_w1  = (const float*)d_in[wb + 8];
    const float* mg_b1  = (const float*)d_in[wb + 9];
    const float* mg_w2  = (const float*)d_in[wb + 10];
    const float* mg_b2  = (const float*)d_in[wb + 11];
    const float* mr_w0  = (const float*)d_in[wb + 12];
    const float* mr_b0  = (const float*)d_in[wb + 13];
    const float* mr_w1  = (const float*)d_in[wb + 14];
    const float* mr_b1  = (const float*)d_in[wb + 15];
    const float* mr_w2  = (const float*)d_in[wb + 16];
    const float* mr_b2  = (const float*)d_in[wb + 17];

    float* x = (float*)d_out;

    cudaFuncSetAttribute(mlp_mma<0>, cudaFuncAttributeMaxDynamicSharedMemorySize, SMEM_MMA_01);
    cudaFuncSetAttribute(mlp_mma<1>, cudaFuncAttributeMaxDynamicSharedMemorySize, SMEM_MMA_01);
    cudaFuncSetAttribute(mlp_mma<2>, cudaFuncAttributeMaxDynamicSharedMemorySize, SMEM_MMA_2);
    cudaFuncSetAttribute(mlp_small<1>, cudaFuncAttributeMaxDynamicSharedMemorySize, SMEM_SMALL);
    cudaFuncSetAttribute(mlp_small<2>, cudaFuncAttributeMaxDynamicSharedMemorySize, SMEM_SMALL);

    // init: only leaf rows need the original x
    leaf_copy_kernel<<<(NL * 32 + 255) / 256, 256>>>(x, x_in);

    // edge-block layout: block 0 = leaf edges (NL), block d (1..13): 8*(NLEAF>>(d-1)) edges
    int cnt[14], st[14];
    cnt[0] = NL; st[0] = 0;
    for (int d = 1; d < DEPTH; ++d) {
        cnt[d] = 8 * (NLEAF >> (d - 1));
        st[d] = st[d - 1] + cnt[d - 1];
    }

    constexpr int SMALL_THRESH = 2048;

    // ---- nem: leaf -> level-1 ----
    mlp_mma<0><<<(NL + 63) / 64, 256, SMEM_MMA_01>>>(
        x, ef, esrc, edst, nullptr,
        nem_w0, nem_b0, nem_w1, nem_b1, nem_w2, nem_b2, 0, 0, NL);

    // ---- mg: upward merge, levels 1..13 (sequential) ----
    for (int d = 1; d < DEPTH; ++d) {
        int half = cnt[d] / 2;
        if (half <= SMALL_THRESH)
            mlp_small<1><<<(half + 15) / 16, 256, SMEM_SMALL>>>(
                x, nullptr, esrc, edst, nullptr,
                mg_w0, mg_b0, mg_w1, mg_b1, mg_w2, mg_b2, st[d], half, half);
        else
            mlp_mma<1><<<(half + 63) / 64, 256, SMEM_MMA_01>>>(
                x, nullptr, esrc, edst, nullptr,
                mg_w0, mg_b0, mg_w1, mg_b1, mg_w2, mg_b2, st[d], half, half);
    }

    // ---- mr: downward, depth 14..1 (sequential) ----
    for (int depth = DEPTH; depth >= 1; --depth) {
        int sE, m;
        if (depth == 1) { sE = 0; m = NL; }
        else            { sE = st[depth - 1]; m = cnt[depth - 1]; }
        if (m <= SMALL_THRESH)
            mlp_small<2><<<(m + 15) / 16, 256, SMEM_SMALL>>>(
                x, nullptr, esrc, edst, est,
                mr_w0, mr_b0, mr_w1, mr_b1, mr_w2, mr_b2, sE, 0, m);
        else
            mlp_mma<2><<<(m + 63) / 64, 256, SMEM_MMA_2>>>(
                x, nullptr, esrc, edst, est,
                mr_w0, mr_b0, mr_w1, mr_b1, mr_w2, mr_b2, sE, 0, m);
    }
}